// round 7
// baseline (speedup 1.0000x reference)
#include <cuda_runtime.h>
#include <cuda_fp16.h>
#include <cstdint>

#define NN 100000
#define EE 1600000
#define F_IN 64
#define F_HID 64
#define F_OUT 32

// Scratch (static device globals — no allocation allowed)
__device__ int   g_degi[NN];
__device__ __align__(16) float g_dis[NN];
__device__ int   g_off[NN];
__device__ int   g_cursor[NN];
__device__ int   g_total;
__device__ int   g_csr_src[EE];
__device__ __align__(16) __half g_h1s[NN * F_HID];  // (x@W1)*dis  (fp16)
__device__ __align__(16) float  g_acc1[NN * F_HID]; // relu(layer-1 out)
__device__ __align__(16) __half g_h2s[NN * F_OUT];  // (acc1@W2)*dis (fp16)

// ---------------------------------------------------------------------------
// CSR build
// ---------------------------------------------------------------------------
__global__ void k_zero() {
    int i = blockIdx.x * blockDim.x + threadIdx.x;
    if (i < NN) g_degi[i] = 0;
    if (i == 0) g_total = 0;
}

__global__ void k_degree(const int4* __restrict__ dst4) {
    int i = blockIdx.x * blockDim.x + threadIdx.x;
    if (i < EE / 4) {
        const int4 d = dst4[i];
        atomicAdd(&g_degi[d.x], 1);
        atomicAdd(&g_degi[d.y], 1);
        atomicAdd(&g_degi[d.z], 1);
        atomicAdd(&g_degi[d.w], 1);
    }
}

__global__ void k_dis_alloc() {
    int i = blockIdx.x * blockDim.x + threadIdx.x;
    if (i < NN) {
        const int d = g_degi[i];
        g_dis[i] = rsqrtf((float)d + 1.0f);
        const int off = atomicAdd(&g_total, d);
        g_off[i] = off;
        g_cursor[i] = off;
    }
}

__global__ void k_fill(const int4* __restrict__ src4,
                       const int4* __restrict__ dst4) {
    int i = blockIdx.x * blockDim.x + threadIdx.x;
    if (i < EE / 4) {
        const int4 s = src4[i];
        const int4 d = dst4[i];
        g_csr_src[atomicAdd(&g_cursor[d.x], 1)] = s.x;
        g_csr_src[atomicAdd(&g_cursor[d.y], 1)] = s.y;
        g_csr_src[atomicAdd(&g_cursor[d.z], 1)] = s.z;
        g_csr_src[atomicAdd(&g_cursor[d.w], 1)] = s.w;
    }
}

// ---------------------------------------------------------------------------
// Layer 1 GEMM: h1s = (x @ W1) * dis[n], stored fp16.
// ---------------------------------------------------------------------------
__global__ void __launch_bounds__(256) k_gemm1(const float* __restrict__ x,
                                               const float* __restrict__ W) {
    __shared__ float Ws[F_IN * F_HID];
    __shared__ __align__(16) float xs[4 * F_IN];

    for (int i = threadIdx.x; i < F_IN * F_HID; i += 256) Ws[i] = W[i];
    __syncthreads();

    const int col = threadIdx.x & 63;
    float w[F_IN];
#pragma unroll
    for (int k = 0; k < F_IN; k++) w[k] = Ws[k * F_HID + col];

    const int ntiles = NN / 4;
    for (int tile = blockIdx.x; tile < ntiles; tile += gridDim.x) {
        const int nb = tile * 4;
        __syncthreads();
        xs[threadIdx.x] = x[nb * F_IN + threadIdx.x];
        __syncthreads();

        float a0 = 0.f, a1 = 0.f, a2 = 0.f, a3 = 0.f;
        const float4* xv = reinterpret_cast<const float4*>(xs);
#pragma unroll
        for (int k4 = 0; k4 < 16; k4++) {
            const float4 r0 = xv[k4];
            const float4 r1 = xv[16 + k4];
            const float4 r2 = xv[32 + k4];
            const float4 r3 = xv[48 + k4];
            const float w0 = w[4 * k4 + 0], w1 = w[4 * k4 + 1];
            const float w2 = w[4 * k4 + 2], w3 = w[4 * k4 + 3];
            a0 = fmaf(r0.x, w0, a0); a0 = fmaf(r0.y, w1, a0);
            a0 = fmaf(r0.z, w2, a0); a0 = fmaf(r0.w, w3, a0);
            a1 = fmaf(r1.x, w0, a1); a1 = fmaf(r1.y, w1, a1);
            a1 = fmaf(r1.z, w2, a1); a1 = fmaf(r1.w, w3, a1);
            a2 = fmaf(r2.x, w0, a2); a2 = fmaf(r2.y, w1, a2);
            a2 = fmaf(r2.z, w2, a2); a2 = fmaf(r2.w, w3, a2);
            a3 = fmaf(r3.x, w0, a3); a3 = fmaf(r3.y, w1, a3);
            a3 = fmaf(r3.z, w2, a3); a3 = fmaf(r3.w, w3, a3);
        }

        g_h1s[(nb + 0) * F_HID + col] = __float2half_rn(a0 * g_dis[nb + 0]);
        g_h1s[(nb + 1) * F_HID + col] = __float2half_rn(a1 * g_dis[nb + 1]);
        g_h1s[(nb + 2) * F_HID + col] = __float2half_rn(a2 * g_dis[nb + 2]);
        g_h1s[(nb + 3) * F_HID + col] = __float2half_rn(a3 * g_dis[nb + 3]);
    }
}

// ---------------------------------------------------------------------------
// Layer 1 aggregation: one warp per dst node. Lane holds 2 columns (half2).
// Indices staged coalesced into registers, distributed via shfl.
// ---------------------------------------------------------------------------
__global__ void __launch_bounds__(256) k_agg1(const float* __restrict__ b1) {
    const int warp = (blockIdx.x * 256 + threadIdx.x) >> 5;
    const int lane = threadIdx.x & 31;
    if (warp >= NN) return;
    const int n   = warp;
    const int off = g_off[n];
    const int deg = g_degi[n];

    const __half2* h2p = reinterpret_cast<const __half2*>(g_h1s);

    float2 acc = __half22float2(h2p[n * 32 + lane]);   // self term

    for (int base = 0; base < deg; base += 32) {
        const int rem = deg - base;
        const int m   = rem < 32 ? rem : 32;
        int idx = 0;
        if (lane < m) idx = g_csr_src[off + base + lane];

        int j = 0;
        for (; j + 4 <= m; j += 4) {
            const int s0 = __shfl_sync(0xffffffffu, idx, j + 0);
            const int s1 = __shfl_sync(0xffffffffu, idx, j + 1);
            const int s2 = __shfl_sync(0xffffffffu, idx, j + 2);
            const int s3 = __shfl_sync(0xffffffffu, idx, j + 3);
            const float2 v0 = __half22float2(h2p[s0 * 32 + lane]);
            const float2 v1 = __half22float2(h2p[s1 * 32 + lane]);
            const float2 v2 = __half22float2(h2p[s2 * 32 + lane]);
            const float2 v3 = __half22float2(h2p[s3 * 32 + lane]);
            acc.x += (v0.x + v1.x) + (v2.x + v3.x);
            acc.y += (v0.y + v1.y) + (v2.y + v3.y);
        }
        for (; j < m; j++) {
            const int s = __shfl_sync(0xffffffffu, idx, j);
            const float2 v = __half22float2(h2p[s * 32 + lane]);
            acc.x += v.x; acc.y += v.y;
        }
    }

    const float dd = g_dis[n];
    const float2 bb = *reinterpret_cast<const float2*>(&b1[lane * 2]);
    float2 o;
    o.x = fmaxf(fmaf(acc.x, dd, bb.x), 0.0f);
    o.y = fmaxf(fmaf(acc.y, dd, bb.y), 0.0f);
    *reinterpret_cast<float2*>(&g_acc1[n * F_HID + lane * 2]) = o;
}

// ---------------------------------------------------------------------------
// Layer 2 GEMM: h2s = (acc1 @ W2) * dis[n], stored fp16.
// ---------------------------------------------------------------------------
__global__ void __launch_bounds__(256) k_gemm2(const float* __restrict__ W) {
    __shared__ float Ws[F_HID * F_OUT];
    __shared__ __align__(16) float xs[8 * F_HID];

    for (int i = threadIdx.x; i < F_HID * F_OUT; i += 256) Ws[i] = W[i];
    __syncthreads();

    const int col = threadIdx.x & 31;
    const int g   = threadIdx.x >> 5;
    float w[F_HID];
#pragma unroll
    for (int k = 0; k < F_HID; k++) w[k] = Ws[k * F_OUT + col];

    const int ntiles = NN / 8;
    for (int tile = blockIdx.x; tile < ntiles; tile += gridDim.x) {
        const int nb = tile * 8;
        __syncthreads();
        xs[threadIdx.x]       = g_acc1[nb * F_HID + threadIdx.x];
        xs[threadIdx.x + 256] = g_acc1[nb * F_HID + 256 + threadIdx.x];
        __syncthreads();

        const int n = nb + g;
        float acc = 0.f;
        const float4* xv = reinterpret_cast<const float4*>(xs + g * F_HID);
#pragma unroll
        for (int k4 = 0; k4 < 16; k4++) {
            const float4 r = xv[k4];
            acc = fmaf(r.x, w[4 * k4 + 0], acc);
            acc = fmaf(r.y, w[4 * k4 + 1], acc);
            acc = fmaf(r.z, w[4 * k4 + 2], acc);
            acc = fmaf(r.w, w[4 * k4 + 3], acc);
        }
        g_h2s[n * F_OUT + col] = __float2half_rn(acc * g_dis[n]);
    }
}

// ---------------------------------------------------------------------------
// Layer 2 aggregation: one warp per dst node; lane holds 1 column.
// ---------------------------------------------------------------------------
__global__ void __launch_bounds__(256) k_agg2(const float* __restrict__ b2,
                                              float* __restrict__ out) {
    const int warp = (blockIdx.x * 256 + threadIdx.x) >> 5;
    const int lane = threadIdx.x & 31;
    if (warp >= NN) return;
    const int n   = warp;
    const int off = g_off[n];
    const int deg = g_degi[n];

    float acc = __half2float(g_h2s[n * F_OUT + lane]);  // self term

    for (int base = 0; base < deg; base += 32) {
        const int rem = deg - base;
        const int m   = rem < 32 ? rem : 32;
        int idx = 0;
        if (lane < m) idx = g_csr_src[off + base + lane];

        int j = 0;
        for (; j + 4 <= m; j += 4) {
            const int s0 = __shfl_sync(0xffffffffu, idx, j + 0);
            const int s1 = __shfl_sync(0xffffffffu, idx, j + 1);
            const int s2 = __shfl_sync(0xffffffffu, idx, j + 2);
            const int s3 = __shfl_sync(0xffffffffu, idx, j + 3);
            const float v0 = __half2float(g_h2s[s0 * F_OUT + lane]);
            const float v1 = __half2float(g_h2s[s1 * F_OUT + lane]);
            const float v2 = __half2float(g_h2s[s2 * F_OUT + lane]);
            const float v3 = __half2float(g_h2s[s3 * F_OUT + lane]);
            acc += (v0 + v1) + (v2 + v3);
        }
        for (; j < m; j++) {
            const int s = __shfl_sync(0xffffffffu, idx, j);
            acc += __half2float(g_h2s[s * F_OUT + lane]);
        }
    }

    out[n * F_OUT + lane] = fmaf(acc, g_dis[n], b2[lane]);
}

// ---------------------------------------------------------------------------
extern "C" void kernel_launch(void* const* d_in, const int* in_sizes, int n_in,
                              void* d_out, int out_size) {
    const float* x  = (const float*)d_in[0];
    const int*   ei = (const int*)d_in[1];   // [2, E] int32 on device
    const float* W1 = (const float*)d_in[2];
    const float* b1 = (const float*)d_in[3];
    const float* W2 = (const float*)d_in[4];
    const float* b2 = (const float*)d_in[5];
    float*       out = (float*)d_out;

    const int4* src4 = (const int4*)ei;
    const int4* dst4 = (const int4*)(ei + EE);

    // CSR build
    k_zero<<<(NN + 255) / 256, 256>>>();
    k_degree<<<(EE / 4 + 255) / 256, 256>>>(dst4);
    k_dis_alloc<<<(NN + 255) / 256, 256>>>();
    k_fill<<<(EE / 4 + 255) / 256, 256>>>(src4, dst4);

    // layer 1
    k_gemm1<<<592, 256>>>(x, W1);
    k_agg1<<<(NN * 32 + 255) / 256, 256>>>(b1);

    // layer 2
    k_gemm2<<<592, 256>>>(W2);
    k_agg2<<<(NN * 32 + 255) / 256, 256>>>(b2, out);
}